// round 4
// baseline (speedup 1.0000x reference)
#include <cuda_runtime.h>
#include <math.h>

#define NMAX 100000
#define DIN  256
#define HH1  256
#define HH2  128

// Scratch (allocation-free rule: __device__ globals)
__device__ float g_hs1 [(size_t)NMAX * HH1];
__device__ float g_agg1[(size_t)NMAX * HH1];
__device__ float g_hs2 [(size_t)NMAX * HH2];
__device__ float g_agg2[(size_t)NMAX * HH2];
__device__ int   g_deg [NMAX];
__device__ float g_dinv[NMAX];

// ---------------------------------------------------------------------------
// Degree / norm
// ---------------------------------------------------------------------------
__global__ void deg_init_kernel(int n) {
    int i = blockIdx.x * blockDim.x + threadIdx.x;
    if (i < n) g_deg[i] = 1;  // self loop
}

__global__ void deg_edge_kernel(const int* __restrict__ dst, int E) {
    for (int e = blockIdx.x * blockDim.x + threadIdx.x; e < E;
         e += gridDim.x * blockDim.x)
        atomicAdd(&g_deg[dst[e]], 1);
}

__global__ void dinv_kernel(int n) {
    int i = blockIdx.x * blockDim.x + threadIdx.x;
    if (i < n) g_dinv[i] = rsqrtf((float)g_deg[i]);
}

// ---------------------------------------------------------------------------
// Fused GEMM (double-buffered, packed fma.rn.f32x2 inner loop):
//   LAYER==1: hs1 = (X @ W1) * dinv[row];           agg1 = hs1  (self-loop init)
//   LAYER==2: A   = relu(dinv[row]*agg1 + b1[k])    (prologue fusion)
//             hs2 = (A @ W2) * dinv[row];           agg2 = hs2
// BM=128, BN=64, BK=16, 256 threads, 8x4 outputs/thread (4 row-pairs x 4 cols).
// ---------------------------------------------------------------------------
template<int LAYER>
__global__ __launch_bounds__(256) void gemm_kernel(
    const float* __restrict__ Ax, const float* __restrict__ B,
    const float* __restrict__ prebias, int M)
{
    constexpr int KD = (LAYER == 1) ? DIN : HH1;
    constexpr int ND = (LAYER == 1) ? HH1 : HH2;
    constexpr bool PRE = (LAYER == 2);
    const float* A  = (LAYER == 1) ? Ax : g_agg1;
    float* hs  = (LAYER == 1) ? g_hs1  : g_hs2;
    float* agg = (LAYER == 1) ? g_agg1 : g_agg2;

    constexpr int BM = 128, BN = 64, BK = 16;
    constexpr int NT = KD / BK;          // 16 tiles
    __shared__ float As[2][BK][BM];
    __shared__ float Bs[2][BK][BN];

    int tid = threadIdx.x;
    int blockM = blockIdx.y * BM;
    int blockN = blockIdx.x * BN;

    int ty = tid >> 4;          // 0..15 -> 8 rows each
    int tx = tid & 15;          // 0..15 -> 4 cols each

    // Packed accumulators: accp[ii][j] holds rows (ty*8+2ii, ty*8+2ii+1), col j
    unsigned long long accp[4][4];
#pragma unroll
    for (int ii = 0; ii < 4; ii++)
#pragma unroll
        for (int j = 0; j < 4; j++) accp[ii][j] = 0ull;  // {0.f, 0.f}

    // load-role indices
    int arow = tid >> 2;        // 0..63 (2 halves of 64 rows)
    int acol = (tid & 3) * 4;   // 0,4,8,12
    int brow = tid >> 4;        // 0..15
    int bcol = (tid & 15) * 4;  // 0..60

    int grow0 = blockM + arow;
    int grow1 = blockM + arow + 64;
    bool ok0 = grow0 < M, ok1 = grow1 < M;
    float dv0 = 0.f, dv1 = 0.f;
    if (PRE) {
        if (ok0) dv0 = g_dinv[grow0];
        if (ok1) dv1 = g_dinv[grow1];
    }

    float4 ra0, ra1, rb;

    // ---- register-stage loader for tile kt ----
    auto load_regs = [&](int kt) {
        ra0 = make_float4(0.f, 0.f, 0.f, 0.f);
        ra1 = make_float4(0.f, 0.f, 0.f, 0.f);
        if (ok0) ra0 = *(const float4*)(A + (size_t)grow0 * KD + kt + acol);
        if (ok1) ra1 = *(const float4*)(A + (size_t)grow1 * KD + kt + acol);
        if (PRE) {
            float4 bb = *(const float4*)(prebias + kt + acol);
            ra0.x = fmaxf(fmaf(dv0, ra0.x, bb.x), 0.f);
            ra0.y = fmaxf(fmaf(dv0, ra0.y, bb.y), 0.f);
            ra0.z = fmaxf(fmaf(dv0, ra0.z, bb.z), 0.f);
            ra0.w = fmaxf(fmaf(dv0, ra0.w, bb.w), 0.f);
            ra1.x = fmaxf(fmaf(dv1, ra1.x, bb.x), 0.f);
            ra1.y = fmaxf(fmaf(dv1, ra1.y, bb.y), 0.f);
            ra1.z = fmaxf(fmaf(dv1, ra1.z, bb.z), 0.f);
            ra1.w = fmaxf(fmaf(dv1, ra1.w, bb.w), 0.f);
        }
        rb = *(const float4*)(B + (size_t)(kt + brow) * ND + blockN + bcol);
    };

    auto store_smem = [&](int buf) {
        As[buf][acol + 0][arow]      = ra0.x;
        As[buf][acol + 1][arow]      = ra0.y;
        As[buf][acol + 2][arow]      = ra0.z;
        As[buf][acol + 3][arow]      = ra0.w;
        As[buf][acol + 0][arow + 64] = ra1.x;
        As[buf][acol + 1][arow + 64] = ra1.y;
        As[buf][acol + 2][arow + 64] = ra1.z;
        As[buf][acol + 3][arow + 64] = ra1.w;
        *(float4*)&Bs[buf][brow][bcol] = rb;
    };

    // prologue: fill buffer 0
    load_regs(0);
    store_smem(0);
    __syncthreads();

#pragma unroll 1
    for (int t = 0; t < NT; t++) {
        int cur = t & 1;
        bool more = (t + 1 < NT);
        if (more) load_regs((t + 1) * BK);   // overlap with compute below

#pragma unroll
        for (int k = 0; k < BK; k++) {
            // A fragment: 8 contiguous rows -> 4 packed f32x2 pairs, straight
            // from two LDS.128 (no pack instructions needed).
            unsigned long long ap[4];
            *(float4*)&ap[0] = *(const float4*)&As[cur][k][ty * 8];      // rows 0,1,2,3
            *(float4*)&ap[2] = *(const float4*)&As[cur][k][ty * 8 + 4];  // rows 4,5,6,7
            float b[4];
            *(float4*)&b[0] = *(const float4*)&Bs[cur][k][tx * 4];
            unsigned long long bp[4];
#pragma unroll
            for (int j = 0; j < 4; j++)
                asm("mov.b64 %0, {%1, %2};" : "=l"(bp[j]) : "f"(b[j]), "f"(b[j]));
#pragma unroll
            for (int ii = 0; ii < 4; ii++)
#pragma unroll
                for (int j = 0; j < 4; j++)
                    asm("fma.rn.f32x2 %0, %1, %2, %3;"
                        : "=l"(accp[ii][j])
                        : "l"(ap[ii]), "l"(bp[j]), "l"(accp[ii][j]));
        }

        if (more) store_smem(cur ^ 1);
        __syncthreads();
    }

    // Epilogue: unpack, scale by dinv[row]; write hs (streaming) + agg (self-loop)
#pragma unroll
    for (int ii = 0; ii < 4; ii++) {
        float lo[4], hi[4];
#pragma unroll
        for (int j = 0; j < 4; j++)
            asm("mov.b64 {%0, %1}, %2;" : "=f"(lo[j]), "=f"(hi[j]) : "l"(accp[ii][j]));
#pragma unroll
        for (int h = 0; h < 2; h++) {
            int r = blockM + ty * 8 + ii * 2 + h;
            if (r < M) {
                float dv = g_dinv[r];
                const float* s = h ? hi : lo;
                float4 o;
                o.x = s[0] * dv; o.y = s[1] * dv;
                o.z = s[2] * dv; o.w = s[3] * dv;
                size_t off = (size_t)r * ND + blockN + tx * 4;
                __stcs((float4*)(hs + off), o);          // read-once stream
                *(float4*)(agg + off) = o;
            }
        }
    }
}

// ---------------------------------------------------------------------------
// Edge scatter: one warp per edge, agg[dst] += hs[src]  (gather + v4 RED)
// Loads hoisted before REDs for MLP per lane.
// ---------------------------------------------------------------------------
template<int LAYER>
__global__ __launch_bounds__(256) void scatter_kernel(
    const int* __restrict__ src, const int* __restrict__ dst, int E)
{
    constexpr int F = (LAYER == 1) ? HH1 : HH2;
    constexpr int NIT = F / 128;   // float4s per lane
    const float* hs = (LAYER == 1) ? g_hs1  : g_hs2;
    float* agg      = (LAYER == 1) ? g_agg1 : g_agg2;

    int g = blockIdx.x * blockDim.x + threadIdx.x;
    int e = g >> 5;
    int lane = g & 31;
    if (e >= E) return;

    int s = __ldg(src + e);
    int d = __ldg(dst + e);
    const float4* sp = (const float4*)(hs + (size_t)s * F);
    float4* dp = (float4*)(agg + (size_t)d * F);

    float4 v[NIT];
#pragma unroll
    for (int i = 0; i < NIT; i++)
        v[i] = __ldg(sp + lane + i * 32);
#pragma unroll
    for (int i = 0; i < NIT; i++)
        asm volatile("red.global.add.v4.f32 [%0], {%1, %2, %3, %4};"
                     :: "l"(dp + lane + i * 32),
                        "f"(v[i].x), "f"(v[i].y), "f"(v[i].z), "f"(v[i].w)
                     : "memory");
}

// ---------------------------------------------------------------------------
// Final: out = dinv[row]*agg2 + b2
// ---------------------------------------------------------------------------
__global__ void finalize_kernel(const float* __restrict__ b2,
                                float* __restrict__ out, int n)
{
    int idx = blockIdx.x * blockDim.x + threadIdx.x;   // over n * HH2/4
    int total = n * (HH2 / 4);
    if (idx >= total) return;
    int i  = idx / (HH2 / 4);
    int j4 = idx % (HH2 / 4);
    float dv = g_dinv[i];
    float4 v  = *(const float4*)(g_agg2 + (size_t)i * HH2 + j4 * 4);
    float4 bb = *(const float4*)(b2 + j4 * 4);
    float4 o;
    o.x = fmaf(dv, v.x, bb.x);
    o.y = fmaf(dv, v.y, bb.y);
    o.z = fmaf(dv, v.z, bb.z);
    o.w = fmaf(dv, v.w, bb.w);
    *(float4*)(out + (size_t)i * HH2 + j4 * 4) = o;
}

// ---------------------------------------------------------------------------
extern "C" void kernel_launch(void* const* d_in, const int* in_sizes, int n_in,
                              void* d_out, int out_size)
{
    const float* x  = (const float*)d_in[0];
    const float* W1 = (const float*)d_in[1];
    const float* b1 = (const float*)d_in[2];
    const float* W2 = (const float*)d_in[3];
    const float* b2 = (const float*)d_in[4];
    const int* edge = (const int*)d_in[5];

    int n = in_sizes[0] / DIN;
    int E = in_sizes[5] / 2;
    const int* src = edge;
    const int* dst = edge + E;
    float* out = (float*)d_out;

    int tb = 256;

    deg_init_kernel<<<(n + tb - 1) / tb, tb>>>(n);
    deg_edge_kernel<<<592, 512>>>(dst, E);   // ~4 blocks/SM grid-stride
    dinv_kernel<<<(n + tb - 1) / tb, tb>>>(n);

    dim3 g1(HH1 / 64, (n + 127) / 128);
    gemm_kernel<1><<<g1, 256>>>(x, W1, nullptr, n);

    long long t1 = (long long)E * 32;
    scatter_kernel<1><<<(unsigned)((t1 + tb - 1) / tb), tb>>>(src, dst, E);

    dim3 g2(HH2 / 64, (n + 127) / 128);
    gemm_kernel<2><<<g2, 256>>>(nullptr, W2, b1, n);

    scatter_kernel<2><<<(unsigned)((t1 + tb - 1) / tb), tb>>>(src, dst, E);

    finalize_kernel<<<(n * (HH2 / 4) + tb - 1) / tb, tb>>>(b2, out, n);
}